// round 2
// baseline (speedup 1.0000x reference)
#include <cuda_runtime.h>
#include <cstdint>

// Shapes (fixed for this problem)
static constexpr int L    = 64;    // tokens per window (TP*W)
static constexpr int ED   = 256;   // embed dim
static constexpr int NWIN = 256;   // f * nW
static constexpr int KC   = 32;    // k-chunk for GEMM1
static constexpr int WPAD = 260;   // padded row stride for transposed Wp chunk
static constexpr int TPB  = 256;

// Scratch for per-window A = deg @ edge_bias  (256 * 64 * 64 floats = 4 MB)
__device__ float g_A[NWIN * L * L];

__device__ __forceinline__ unsigned long long pack2(float lo, float hi) {
    unsigned long long r;
    asm("mov.b64 %0, {%1, %2};" : "=l"(r) : "f"(lo), "f"(hi));
    return r;
}
__device__ __forceinline__ unsigned long long fma2(unsigned long long a,
                                                   unsigned long long b,
                                                   unsigned long long c) {
    unsigned long long d;
    asm("fma.rn.f32x2 %0, %1, %2, %3;" : "=l"(d) : "l"(a), "l"(b), "l"(c));
    return d;
}
__device__ __forceinline__ float lo32(unsigned long long v) {
    return __uint_as_float((unsigned)(v & 0xffffffffull));
}
__device__ __forceinline__ float hi32(unsigned long long v) {
    return __uint_as_float((unsigned)(v >> 32));
}

// ---------------------------------------------------------------------------
// Kernel A: A_w = deg_mat[w] @ edge_bias[w]   (256 windows, 64x64x64 each)
// ---------------------------------------------------------------------------
__global__ __launch_bounds__(TPB) void precompute_A_kernel(
    const float* __restrict__ deg, const float* __restrict__ eb)
{
    __shared__ float sD[L][L];
    __shared__ float sE[L][L + 1];
    const int w = blockIdx.x;
    const float* dw = deg + (size_t)w * L * L;
    const float* ew = eb + (size_t)w * L * L;
    for (int i = threadIdx.x; i < L * L; i += TPB) {
        sD[i >> 6][i & 63] = dw[i];
        sE[i >> 6][i & 63] = ew[i];
    }
    __syncthreads();
    const int tp = threadIdx.x >> 4;   // 0..15 -> rows tp*4..tp*4+3
    const int tq = threadIdx.x & 15;   // 0..15 -> cols tq*4..tq*4+3
    float acc[4][4];
    #pragma unroll
    for (int i = 0; i < 4; ++i)
        #pragma unroll
        for (int j = 0; j < 4; ++j) acc[i][j] = 0.0f;

    #pragma unroll 8
    for (int k = 0; k < L; ++k) {
        float a0 = sD[tp * 4 + 0][k];
        float a1 = sD[tp * 4 + 1][k];
        float a2 = sD[tp * 4 + 2][k];
        float a3 = sD[tp * 4 + 3][k];
        float b0 = sE[k][tq * 4 + 0];
        float b1 = sE[k][tq * 4 + 1];
        float b2 = sE[k][tq * 4 + 2];
        float b3 = sE[k][tq * 4 + 3];
        acc[0][0] += a0 * b0; acc[0][1] += a0 * b1; acc[0][2] += a0 * b2; acc[0][3] += a0 * b3;
        acc[1][0] += a1 * b0; acc[1][1] += a1 * b1; acc[1][2] += a1 * b2; acc[1][3] += a1 * b3;
        acc[2][0] += a2 * b0; acc[2][1] += a2 * b1; acc[2][2] += a2 * b2; acc[2][3] += a2 * b3;
        acc[3][0] += a3 * b0; acc[3][1] += a3 * b1; acc[3][2] += a3 * b2; acc[3][3] += a3 * b3;
    }
    float* Ao = g_A + (size_t)w * L * L;
    #pragma unroll
    for (int i = 0; i < 4; ++i)
        #pragma unroll
        for (int j = 0; j < 4; ++j)
            Ao[(tp * 4 + i) * L + (tq * 4 + j)] = acc[i][j];
}

// ---------------------------------------------------------------------------
// Kernel B: one block per window.
//   LN(xw) -> sX;  y = sX @ Wp^T + bp (8x8 reg tile, f32x2 FMA);
//   y -> sX (reuse); z = A_w @ y; windowed write-back.
// ---------------------------------------------------------------------------
__global__ __launch_bounds__(TPB, 2) void window_kernel(
    const float* __restrict__ x,
    const float* __restrict__ gamma,
    const float* __restrict__ beta,
    const float* __restrict__ Wp,
    const float* __restrict__ bp,
    float* __restrict__ out)
{
    extern __shared__ float smem[];
    float* sX = smem;                       // [L][ED]   64 KB (xn, later y)
    float* sW = smem + L * ED;              // [KC][WPAD] 33.3 KB (Wp^T chunk)
    float* sA = sW + KC * WPAD;             // [L][L]    16 KB

    const int n  = blockIdx.x;
    const int wi = n & 3;
    const int fi = (n >> 2) & 63;
    const int b  = n >> 8;
    const int w  = fi * 4 + wi;

    const size_t base = (((size_t)b * 256 + (size_t)fi * 4) * 64 + (size_t)wi * 16) * 256;
    const float* xbase = x + base;
    float*       obase = out + base;

    const int warp = threadIdx.x >> 5;
    const int lane = threadIdx.x & 31;

    // Load A_w into smem (needed only for GEMM2; covered by later barriers)
    const float* Aw = g_A + (size_t)w * L * L;
    #pragma unroll
    for (int i = threadIdx.x; i < L * L; i += TPB) sA[i] = Aw[i];

    // gamma/beta for this lane's fixed channel set
    float4 ga0 = *(const float4*)(gamma + lane * 4);
    float4 ga1 = *(const float4*)(gamma + 128 + lane * 4);
    float4 bt0 = *(const float4*)(beta  + lane * 4);
    float4 bt1 = *(const float4*)(beta  + 128 + lane * 4);

    // ---- LayerNorm: warp handles tokens warp*8 .. warp*8+7 ----
    #pragma unroll
    for (int t = 0; t < 8; ++t) {
        const int l = warp * 8 + t;
        const float* row = xbase + (((l >> 4) * 64 + (l & 15)) << 8);
        float4 v0 = *(const float4*)(row + lane * 4);
        float4 v1 = *(const float4*)(row + 128 + lane * 4);
        float s  = v0.x + v0.y + v0.z + v0.w + v1.x + v1.y + v1.z + v1.w;
        float s2 = v0.x * v0.x + v0.y * v0.y + v0.z * v0.z + v0.w * v0.w
                 + v1.x * v1.x + v1.y * v1.y + v1.z * v1.z + v1.w * v1.w;
        #pragma unroll
        for (int o = 16; o > 0; o >>= 1) {
            s  += __shfl_xor_sync(0xffffffffu, s,  o);
            s2 += __shfl_xor_sync(0xffffffffu, s2, o);
        }
        const float mu   = s * (1.0f / ED);
        const float var  = s2 * (1.0f / ED) - mu * mu;
        const float rstd = rsqrtf(var + 1e-5f);
        float4 o0, o1;
        o0.x = (v0.x - mu) * rstd * ga0.x + bt0.x;
        o0.y = (v0.y - mu) * rstd * ga0.y + bt0.y;
        o0.z = (v0.z - mu) * rstd * ga0.z + bt0.z;
        o0.w = (v0.w - mu) * rstd * ga0.w + bt0.w;
        o1.x = (v1.x - mu) * rstd * ga1.x + bt1.x;
        o1.y = (v1.y - mu) * rstd * ga1.y + bt1.y;
        o1.z = (v1.z - mu) * rstd * ga1.z + bt1.z;
        o1.w = (v1.w - mu) * rstd * ga1.w + bt1.w;
        *(float4*)(sX + l * ED + lane * 4)       = o0;
        *(float4*)(sX + l * ED + 128 + lane * 4) = o1;
    }
    __syncthreads();

    // ---- GEMM1: y[l][j] = sum_k xn[l][k] * Wp[j][k] + bp[j] ----
    // thread (tl=warp, tj=lane) owns rows tl*8..+7, cols tj*8..+7
    const int tl = warp;
    const int tj = lane;
    unsigned long long c[8][4];
    {
        float4 bb0 = *(const float4*)(bp + tj * 8);
        float4 bb1 = *(const float4*)(bp + tj * 8 + 4);
        unsigned long long q0 = pack2(bb0.x, bb0.y);
        unsigned long long q1 = pack2(bb0.z, bb0.w);
        unsigned long long q2 = pack2(bb1.x, bb1.y);
        unsigned long long q3 = pack2(bb1.z, bb1.w);
        #pragma unroll
        for (int il = 0; il < 8; ++il) {
            c[il][0] = q0; c[il][1] = q1; c[il][2] = q2; c[il][3] = q3;
        }
    }

    for (int k0 = 0; k0 < ED; k0 += KC) {
        // stage Wp chunk transposed: sW[kk][j] = Wp[j][k0+kk]
        // gmem: float4 per thread per iter; smem stores conflict-free (bank = t%32)
        #pragma unroll
        for (int it = 0; it < 8; ++it) {
            float4 v = *(const float4*)(Wp + (size_t)threadIdx.x * ED + k0 + it * 4);
            sW[(it * 4 + 0) * WPAD + threadIdx.x] = v.x;
            sW[(it * 4 + 1) * WPAD + threadIdx.x] = v.y;
            sW[(it * 4 + 2) * WPAD + threadIdx.x] = v.z;
            sW[(it * 4 + 3) * WPAD + threadIdx.x] = v.w;
        }
        __syncthreads();
        #pragma unroll 8
        for (int kk = 0; kk < KC; ++kk) {
            const float* wr = sW + kk * WPAD + tj * 8;
            float4 b0 = *(const float4*)(wr);
            float4 b1 = *(const float4*)(wr + 4);
            unsigned long long bq0 = pack2(b0.x, b0.y);
            unsigned long long bq1 = pack2(b0.z, b0.w);
            unsigned long long bq2 = pack2(b1.x, b1.y);
            unsigned long long bq3 = pack2(b1.z, b1.w);
            #pragma unroll
            for (int il = 0; il < 8; ++il) {
                float a = sX[(tl * 8 + il) * ED + k0 + kk];   // warp-broadcast
                unsigned long long aq = pack2(a, a);
                c[il][0] = fma2(aq, bq0, c[il][0]);
                c[il][1] = fma2(aq, bq1, c[il][1]);
                c[il][2] = fma2(aq, bq2, c[il][2]);
                c[il][3] = fma2(aq, bq3, c[il][3]);
            }
        }
        __syncthreads();
    }

    // ---- stage y back into sX (xn dead) ----
    #pragma unroll
    for (int il = 0; il < 8; ++il) {
        float* yr = sX + (tl * 8 + il) * ED + tj * 8;
        float4 o0 = make_float4(lo32(c[il][0]), hi32(c[il][0]),
                                lo32(c[il][1]), hi32(c[il][1]));
        float4 o1 = make_float4(lo32(c[il][2]), hi32(c[il][2]),
                                lo32(c[il][3]), hi32(c[il][3]));
        *(float4*)(yr)     = o0;
        *(float4*)(yr + 4) = o1;
    }
    __syncthreads();

    // ---- GEMM2: z[p][j] = sum_q A[p][q] * y[q][j] ----
    #pragma unroll
    for (int il = 0; il < 8; ++il) {
        c[il][0] = 0ull; c[il][1] = 0ull; c[il][2] = 0ull; c[il][3] = 0ull;
    }
    #pragma unroll 8
    for (int q = 0; q < L; ++q) {
        const float* yr = sX + q * ED + tj * 8;
        float4 b0 = *(const float4*)(yr);
        float4 b1 = *(const float4*)(yr + 4);
        unsigned long long bq0 = pack2(b0.x, b0.y);
        unsigned long long bq1 = pack2(b0.z, b0.w);
        unsigned long long bq2 = pack2(b1.x, b1.y);
        unsigned long long bq3 = pack2(b1.z, b1.w);
        #pragma unroll
        for (int il = 0; il < 8; ++il) {
            float a = sA[(tl * 8 + il) * L + q];   // warp-broadcast
            unsigned long long aq = pack2(a, a);
            c[il][0] = fma2(aq, bq0, c[il][0]);
            c[il][1] = fma2(aq, bq1, c[il][1]);
            c[il][2] = fma2(aq, bq2, c[il][2]);
            c[il][3] = fma2(aq, bq3, c[il][3]);
        }
    }

    // ---- windowed write-back ----
    #pragma unroll
    for (int il = 0; il < 8; ++il) {
        const int p = tl * 8 + il;
        float* orow = obase + (((p >> 4) * 64 + (p & 15)) << 8) + tj * 8;
        float4 o0 = make_float4(lo32(c[il][0]), hi32(c[il][0]),
                                lo32(c[il][1]), hi32(c[il][1]));
        float4 o1 = make_float4(lo32(c[il][2]), hi32(c[il][2]),
                                lo32(c[il][3]), hi32(c[il][3]));
        *(float4*)(orow)     = o0;
        *(float4*)(orow + 4) = o1;
    }
}

// ---------------------------------------------------------------------------
extern "C" void kernel_launch(void* const* d_in, const int* in_sizes, int n_in,
                              void* d_out, int out_size)
{
    (void)in_sizes; (void)n_in; (void)out_size;
    const float* x     = (const float*)d_in[0];
    const float* gamma = (const float*)d_in[1];
    const float* beta  = (const float*)d_in[2];
    const float* Wp    = (const float*)d_in[3];
    const float* bp    = (const float*)d_in[4];
    const float* eb    = (const float*)d_in[5];
    const float* deg   = (const float*)d_in[6];
    float* out = (float*)d_out;

    const size_t smem_bytes = (size_t)(L * ED + KC * WPAD + L * L) * sizeof(float); // 115200
    cudaFuncSetAttribute(window_kernel,
                         cudaFuncAttributeMaxDynamicSharedMemorySize,
                         (int)smem_bytes);

    precompute_A_kernel<<<NWIN, TPB>>>(deg, eb);
    window_kernel<<<2048, TPB, smem_bytes>>>(x, gamma, beta, Wp, bp, out);
}

// round 3
// speedup vs baseline: 1.0230x; 1.0230x over previous
#include <cuda_runtime.h>
#include <cstdint>

// Shapes (fixed for this problem)
static constexpr int L    = 64;    // tokens per window (TP*W)
static constexpr int ED   = 256;   // embed dim
static constexpr int NWIN = 256;   // f * nW
static constexpr int KC   = 32;    // k-chunk for GEMM1
static constexpr int WPAD = 260;   // padded row stride for transposed Wp chunk
static constexpr int TPB  = 256;

// Scratch for per-window A = deg @ edge_bias  (256 * 64 * 64 floats = 4 MB)
__device__ float g_A[NWIN * L * L];

__device__ __forceinline__ unsigned long long pack2(float lo, float hi) {
    unsigned long long r;
    asm("mov.b64 %0, {%1, %2};" : "=l"(r) : "f"(lo), "f"(hi));
    return r;
}
__device__ __forceinline__ unsigned long long fma2(unsigned long long a,
                                                   unsigned long long b,
                                                   unsigned long long c) {
    unsigned long long d;
    asm("fma.rn.f32x2 %0, %1, %2, %3;" : "=l"(d) : "l"(a), "l"(b), "l"(c));
    return d;
}
__device__ __forceinline__ float lo32(unsigned long long v) {
    return __uint_as_float((unsigned)(v & 0xffffffffull));
}
__device__ __forceinline__ float hi32(unsigned long long v) {
    return __uint_as_float((unsigned)(v >> 32));
}

// ---------------------------------------------------------------------------
// Kernel A: A_w = deg_mat[w] @ edge_bias[w]   (256 windows, 64x64x64 each)
// ---------------------------------------------------------------------------
__global__ __launch_bounds__(TPB) void precompute_A_kernel(
    const float* __restrict__ deg, const float* __restrict__ eb)
{
    __shared__ float sD[L][L];
    __shared__ float sE[L][L + 1];
    const int w = blockIdx.x;
    const float* dw = deg + (size_t)w * L * L;
    const float* ew = eb + (size_t)w * L * L;
    for (int i = threadIdx.x; i < L * L; i += TPB) {
        sD[i >> 6][i & 63] = dw[i];
        sE[i >> 6][i & 63] = ew[i];
    }
    __syncthreads();
    const int tp = threadIdx.x >> 4;
    const int tq = threadIdx.x & 15;
    float acc[4][4];
    #pragma unroll
    for (int i = 0; i < 4; ++i)
        #pragma unroll
        for (int j = 0; j < 4; ++j) acc[i][j] = 0.0f;

    #pragma unroll 8
    for (int k = 0; k < L; ++k) {
        float a0 = sD[tp * 4 + 0][k];
        float a1 = sD[tp * 4 + 1][k];
        float a2 = sD[tp * 4 + 2][k];
        float a3 = sD[tp * 4 + 3][k];
        float b0 = sE[k][tq * 4 + 0];
        float b1 = sE[k][tq * 4 + 1];
        float b2 = sE[k][tq * 4 + 2];
        float b3 = sE[k][tq * 4 + 3];
        acc[0][0] += a0 * b0; acc[0][1] += a0 * b1; acc[0][2] += a0 * b2; acc[0][3] += a0 * b3;
        acc[1][0] += a1 * b0; acc[1][1] += a1 * b1; acc[1][2] += a1 * b2; acc[1][3] += a1 * b3;
        acc[2][0] += a2 * b0; acc[2][1] += a2 * b1; acc[2][2] += a2 * b2; acc[2][3] += a2 * b3;
        acc[3][0] += a3 * b0; acc[3][1] += a3 * b1; acc[3][2] += a3 * b2; acc[3][3] += a3 * b3;
    }
    float* Ao = g_A + (size_t)w * L * L;
    #pragma unroll
    for (int i = 0; i < 4; ++i)
        #pragma unroll
        for (int j = 0; j < 4; ++j)
            Ao[(tp * 4 + i) * L + (tq * 4 + j)] = acc[i][j];
}

// ---------------------------------------------------------------------------
// Kernel B: one block per window.
// ---------------------------------------------------------------------------
__global__ __launch_bounds__(TPB, 2) void window_kernel(
    const float* __restrict__ x,
    const float* __restrict__ gamma,
    const float* __restrict__ beta,
    const float* __restrict__ Wp,
    const float* __restrict__ bp,
    float* __restrict__ out)
{
    extern __shared__ float smem[];
    float* sX = smem;                       // [L][ED]   64 KB (xn, later y)
    float* sW = smem + L * ED;              // [KC][WPAD] 33.3 KB (Wp^T chunk)
    float* sA = sW + KC * WPAD;             // [L][L]    16 KB

    const int n  = blockIdx.x;
    const int wi = n & 3;
    const int fi = (n >> 2) & 63;
    const int b  = n >> 8;
    const int w  = fi * 4 + wi;

    const size_t base = (((size_t)b * 256 + (size_t)fi * 4) * 64 + (size_t)wi * 16) * 256;
    const float* xbase = x + base;
    float*       obase = out + base;

    const int warp = threadIdx.x >> 5;
    const int lane = threadIdx.x & 31;

    // Load A_w into smem (only needed for GEMM2; covered by later barriers)
    const float* Aw = g_A + (size_t)w * L * L;
    #pragma unroll
    for (int i = threadIdx.x; i < L * L; i += TPB) sA[i] = Aw[i];

    // gamma/beta for this lane's fixed channel set
    float4 ga0 = *(const float4*)(gamma + lane * 4);
    float4 ga1 = *(const float4*)(gamma + 128 + lane * 4);
    float4 bt0 = *(const float4*)(beta  + lane * 4);
    float4 bt1 = *(const float4*)(beta  + 128 + lane * 4);

    // ---- LayerNorm: warp handles tokens warp*8 .. warp*8+7 ----
    #pragma unroll
    for (int t = 0; t < 8; ++t) {
        const int l = warp * 8 + t;
        const float* row = xbase + (((l >> 4) * 64 + (l & 15)) << 8);
        float4 v0 = *(const float4*)(row + lane * 4);
        float4 v1 = *(const float4*)(row + 128 + lane * 4);
        float s  = v0.x + v0.y + v0.z + v0.w + v1.x + v1.y + v1.z + v1.w;
        float s2 = v0.x * v0.x + v0.y * v0.y + v0.z * v0.z + v0.w * v0.w
                 + v1.x * v1.x + v1.y * v1.y + v1.z * v1.z + v1.w * v1.w;
        #pragma unroll
        for (int o = 16; o > 0; o >>= 1) {
            s  += __shfl_xor_sync(0xffffffffu, s,  o);
            s2 += __shfl_xor_sync(0xffffffffu, s2, o);
        }
        const float mu   = s * (1.0f / ED);
        const float var  = s2 * (1.0f / ED) - mu * mu;
        const float rstd = rsqrtf(var + 1e-5f);
        float4 o0, o1;
        o0.x = (v0.x - mu) * rstd * ga0.x + bt0.x;
        o0.y = (v0.y - mu) * rstd * ga0.y + bt0.y;
        o0.z = (v0.z - mu) * rstd * ga0.z + bt0.z;
        o0.w = (v0.w - mu) * rstd * ga0.w + bt0.w;
        o1.x = (v1.x - mu) * rstd * ga1.x + bt1.x;
        o1.y = (v1.y - mu) * rstd * ga1.y + bt1.y;
        o1.z = (v1.z - mu) * rstd * ga1.z + bt1.z;
        o1.w = (v1.w - mu) * rstd * ga1.w + bt1.w;
        *(float4*)(sX + l * ED + lane * 4)       = o0;
        *(float4*)(sX + l * ED + 128 + lane * 4) = o1;
    }
    __syncthreads();

    // ---- GEMM1: y[l][j] = sum_k xn[l][k] * Wp[j][k] + bp[j] ----
    // thread (tl=warp, tj=lane) owns rows tl*8..+7, cols tj*8..+7
    const int tl = warp;
    const int tj = lane;
    unsigned long long c[8][4];
    {
        float4 bb0 = *(const float4*)(bp + tj * 8);
        float4 bb1 = *(const float4*)(bp + tj * 8 + 4);
        unsigned long long q0 = pack2(bb0.x, bb0.y);
        unsigned long long q1 = pack2(bb0.z, bb0.w);
        unsigned long long q2 = pack2(bb1.x, bb1.y);
        unsigned long long q3 = pack2(bb1.z, bb1.w);
        #pragma unroll
        for (int il = 0; il < 8; ++il) {
            c[il][0] = q0; c[il][1] = q1; c[il][2] = q2; c[il][3] = q3;
        }
    }

    const float* sXrow = sX + tl * 8 * ED;   // this thread's 8 rows

    for (int k0 = 0; k0 < ED; k0 += KC) {
        // stage Wp chunk transposed: sW[kk][j] = Wp[j][k0+kk]
        #pragma unroll
        for (int it = 0; it < 8; ++it) {
            float4 v = *(const float4*)(Wp + (size_t)threadIdx.x * ED + k0 + it * 4);
            sW[(it * 4 + 0) * WPAD + threadIdx.x] = v.x;
            sW[(it * 4 + 1) * WPAD + threadIdx.x] = v.y;
            sW[(it * 4 + 2) * WPAD + threadIdx.x] = v.z;
            sW[(it * 4 + 3) * WPAD + threadIdx.x] = v.w;
        }
        __syncthreads();
        #pragma unroll 4
        for (int kk = 0; kk < KC; kk += 2) {
            // vectorized broadcast A-loads: one LDS.64 per row covers 2 k-steps
            float2 a2[8];
            #pragma unroll
            for (int il = 0; il < 8; ++il)
                a2[il] = *(const float2*)(sXrow + il * ED + k0 + kk);
            #pragma unroll
            for (int u = 0; u < 2; ++u) {
                const float* wr = sW + (kk + u) * WPAD + tj * 8;
                float4 b0 = *(const float4*)(wr);
                float4 b1 = *(const float4*)(wr + 4);
                unsigned long long bq0 = pack2(b0.x, b0.y);
                unsigned long long bq1 = pack2(b0.z, b0.w);
                unsigned long long bq2 = pack2(b1.x, b1.y);
                unsigned long long bq3 = pack2(b1.z, b1.w);
                #pragma unroll
                for (int il = 0; il < 8; ++il) {
                    const float a = (u == 0) ? a2[il].x : a2[il].y;
                    unsigned long long aq = pack2(a, a);
                    c[il][0] = fma2(aq, bq0, c[il][0]);
                    c[il][1] = fma2(aq, bq1, c[il][1]);
                    c[il][2] = fma2(aq, bq2, c[il][2]);
                    c[il][3] = fma2(aq, bq3, c[il][3]);
                }
            }
        }
        __syncthreads();
    }

    // ---- stage y back into sX (xn dead) ----
    #pragma unroll
    for (int il = 0; il < 8; ++il) {
        float* yr = sX + (tl * 8 + il) * ED + tj * 8;
        float4 o0 = make_float4(lo32(c[il][0]), hi32(c[il][0]),
                                lo32(c[il][1]), hi32(c[il][1]));
        float4 o1 = make_float4(lo32(c[il][2]), hi32(c[il][2]),
                                lo32(c[il][3]), hi32(c[il][3]));
        *(float4*)(yr)     = o0;
        *(float4*)(yr + 4) = o1;
    }
    __syncthreads();

    // ---- GEMM2: z[p][j] = sum_q A[p][q] * y[q][j] ----
    #pragma unroll
    for (int il = 0; il < 8; ++il) {
        c[il][0] = 0ull; c[il][1] = 0ull; c[il][2] = 0ull; c[il][3] = 0ull;
    }
    const float* sArow = sA + tl * 8 * L;
    #pragma unroll 4
    for (int q = 0; q < L; q += 2) {
        float2 a2[8];
        #pragma unroll
        for (int il = 0; il < 8; ++il)
            a2[il] = *(const float2*)(sArow + il * L + q);
        #pragma unroll
        for (int u = 0; u < 2; ++u) {
            const float* yr = sX + (q + u) * ED + tj * 8;
            float4 b0 = *(const float4*)(yr);
            float4 b1 = *(const float4*)(yr + 4);
            unsigned long long bq0 = pack2(b0.x, b0.y);
            unsigned long long bq1 = pack2(b0.z, b0.w);
            unsigned long long bq2 = pack2(b1.x, b1.y);
            unsigned long long bq3 = pack2(b1.z, b1.w);
            #pragma unroll
            for (int il = 0; il < 8; ++il) {
                const float a = (u == 0) ? a2[il].x : a2[il].y;
                unsigned long long aq = pack2(a, a);
                c[il][0] = fma2(aq, bq0, c[il][0]);
                c[il][1] = fma2(aq, bq1, c[il][1]);
                c[il][2] = fma2(aq, bq2, c[il][2]);
                c[il][3] = fma2(aq, bq3, c[il][3]);
            }
        }
    }

    // ---- windowed write-back ----
    #pragma unroll
    for (int il = 0; il < 8; ++il) {
        const int p = tl * 8 + il;
        float* orow = obase + (((p >> 4) * 64 + (p & 15)) << 8) + tj * 8;
        float4 o0 = make_float4(lo32(c[il][0]), hi32(c[il][0]),
                                lo32(c[il][1]), hi32(c[il][1]));
        float4 o1 = make_float4(lo32(c[il][2]), hi32(c[il][2]),
                                lo32(c[il][3]), hi32(c[il][3]));
        *(float4*)(orow)     = o0;
        *(float4*)(orow + 4) = o1;
    }
}

// ---------------------------------------------------------------------------
extern "C" void kernel_launch(void* const* d_in, const int* in_sizes, int n_in,
                              void* d_out, int out_size)
{
    (void)in_sizes; (void)n_in; (void)out_size;
    const float* x     = (const float*)d_in[0];
    const float* gamma = (const float*)d_in[1];
    const float* beta  = (const float*)d_in[2];
    const float* Wp    = (const float*)d_in[3];
    const float* bp    = (const float*)d_in[4];
    const float* eb    = (const float*)d_in[5];
    const float* deg   = (const float*)d_in[6];
    float* out = (float*)d_out;

    const size_t smem_bytes = (size_t)(L * ED + KC * WPAD + L * L) * sizeof(float); // 115200
    cudaFuncSetAttribute(window_kernel,
                         cudaFuncAttributeMaxDynamicSharedMemorySize,
                         (int)smem_bytes);

    precompute_A_kernel<<<NWIN, TPB>>>(deg, eb);
    window_kernel<<<2048, TPB, smem_bytes>>>(x, gamma, beta, Wp, bp, out);
}

// round 4
// speedup vs baseline: 1.0583x; 1.0345x over previous
#include <cuda_runtime.h>
#include <cstdint>

// Shapes (fixed for this problem)
static constexpr int L    = 64;    // tokens per window (TP*W)
static constexpr int ED   = 256;   // embed dim
static constexpr int NWIN = 256;   // f * nW
static constexpr int KC   = 32;    // k-chunk for GEMM1
static constexpr int WPAD = 260;   // padded row stride for transposed Wp chunk
static constexpr int TPB  = 256;

// Scratch for per-window A = deg @ edge_bias  (256 * 64 * 64 floats = 4 MB)
__device__ float g_A[NWIN * L * L];

__device__ __forceinline__ unsigned long long pack2(float lo, float hi) {
    unsigned long long r;
    asm("mov.b64 %0, {%1, %2};" : "=l"(r) : "f"(lo), "f"(hi));
    return r;
}
__device__ __forceinline__ unsigned long long fma2(unsigned long long a,
                                                   unsigned long long b,
                                                   unsigned long long c) {
    unsigned long long d;
    asm("fma.rn.f32x2 %0, %1, %2, %3;" : "=l"(d) : "l"(a), "l"(b), "l"(c));
    return d;
}
__device__ __forceinline__ float lo32(unsigned long long v) {
    return __uint_as_float((unsigned)(v & 0xffffffffull));
}
__device__ __forceinline__ float hi32(unsigned long long v) {
    return __uint_as_float((unsigned)(v >> 32));
}

// ---------------------------------------------------------------------------
// Kernel A: A_w = deg_mat[w] @ edge_bias[w]   (256 windows, 64x64x64 each)
// ---------------------------------------------------------------------------
__global__ __launch_bounds__(TPB) void precompute_A_kernel(
    const float* __restrict__ deg, const float* __restrict__ eb)
{
    __shared__ float sD[L][L];
    __shared__ float sE[L][L + 1];
    const int w = blockIdx.x;
    const float* dw = deg + (size_t)w * L * L;
    const float* ew = eb + (size_t)w * L * L;
    for (int i = threadIdx.x; i < L * L; i += TPB) {
        sD[i >> 6][i & 63] = dw[i];
        sE[i >> 6][i & 63] = ew[i];
    }
    __syncthreads();
    const int tp = threadIdx.x >> 4;
    const int tq = threadIdx.x & 15;
    float acc[4][4];
    #pragma unroll
    for (int i = 0; i < 4; ++i)
        #pragma unroll
        for (int j = 0; j < 4; ++j) acc[i][j] = 0.0f;

    #pragma unroll 8
    for (int k = 0; k < L; ++k) {
        float a0 = sD[tp * 4 + 0][k];
        float a1 = sD[tp * 4 + 1][k];
        float a2 = sD[tp * 4 + 2][k];
        float a3 = sD[tp * 4 + 3][k];
        float b0 = sE[k][tq * 4 + 0];
        float b1 = sE[k][tq * 4 + 1];
        float b2 = sE[k][tq * 4 + 2];
        float b3 = sE[k][tq * 4 + 3];
        acc[0][0] += a0 * b0; acc[0][1] += a0 * b1; acc[0][2] += a0 * b2; acc[0][3] += a0 * b3;
        acc[1][0] += a1 * b0; acc[1][1] += a1 * b1; acc[1][2] += a1 * b2; acc[1][3] += a1 * b3;
        acc[2][0] += a2 * b0; acc[2][1] += a2 * b1; acc[2][2] += a2 * b2; acc[2][3] += a2 * b3;
        acc[3][0] += a3 * b0; acc[3][1] += a3 * b1; acc[3][2] += a3 * b2; acc[3][3] += a3 * b3;
    }
    float* Ao = g_A + (size_t)w * L * L;
    #pragma unroll
    for (int i = 0; i < 4; ++i)
        #pragma unroll
        for (int j = 0; j < 4; ++j)
            Ao[(tp * 4 + i) * L + (tq * 4 + j)] = acc[i][j];
}

// ---------------------------------------------------------------------------
// Kernel B: one block per window.
// Thread (warp tl, lane tj) owns rows tl*8..+7 and columns
// {4*tj..4*tj+3} U {128+4*tj..128+4*tj+3}  (conflict-free LDS.128 fragments)
// ---------------------------------------------------------------------------
__global__ __launch_bounds__(TPB, 2) void window_kernel(
    const float* __restrict__ x,
    const float* __restrict__ gamma,
    const float* __restrict__ beta,
    const float* __restrict__ Wp,
    const float* __restrict__ bp,
    float* __restrict__ out)
{
    extern __shared__ float smem[];
    float* sX = smem;                       // [L][ED]   64 KB (xn, later y)
    float* sW = smem + L * ED;              // [KC][WPAD] 33.3 KB (Wp^T chunk)
    float* sA = sW + KC * WPAD;             // [L][L]    16 KB

    const int n  = blockIdx.x;
    const int wi = n & 3;
    const int fi = (n >> 2) & 63;
    const int b  = n >> 8;
    const int w  = fi * 4 + wi;

    const size_t base = (((size_t)b * 256 + (size_t)fi * 4) * 64 + (size_t)wi * 16) * 256;
    const float* xbase = x + base;
    float*       obase = out + base;

    const int warp = threadIdx.x >> 5;
    const int lane = threadIdx.x & 31;

    // Load A_w into smem (only needed for GEMM2; covered by later barriers)
    const float* Aw = g_A + (size_t)w * L * L;
    #pragma unroll
    for (int i = threadIdx.x; i < L * L; i += TPB) sA[i] = Aw[i];

    // gamma/beta for this lane's fixed channel set
    float4 ga0 = *(const float4*)(gamma + lane * 4);
    float4 ga1 = *(const float4*)(gamma + 128 + lane * 4);
    float4 bt0 = *(const float4*)(beta  + lane * 4);
    float4 bt1 = *(const float4*)(beta  + 128 + lane * 4);

    // ---- LayerNorm: warp handles tokens warp*8 .. warp*8+7 ----
    #pragma unroll
    for (int t = 0; t < 8; ++t) {
        const int l = warp * 8 + t;
        const float* row = xbase + (((l >> 4) * 64 + (l & 15)) << 8);
        float4 v0 = *(const float4*)(row + lane * 4);
        float4 v1 = *(const float4*)(row + 128 + lane * 4);
        float s  = v0.x + v0.y + v0.z + v0.w + v1.x + v1.y + v1.z + v1.w;
        float s2 = v0.x * v0.x + v0.y * v0.y + v0.z * v0.z + v0.w * v0.w
                 + v1.x * v1.x + v1.y * v1.y + v1.z * v1.z + v1.w * v1.w;
        #pragma unroll
        for (int o = 16; o > 0; o >>= 1) {
            s  += __shfl_xor_sync(0xffffffffu, s,  o);
            s2 += __shfl_xor_sync(0xffffffffu, s2, o);
        }
        const float mu   = s * (1.0f / ED);
        const float var  = s2 * (1.0f / ED) - mu * mu;
        const float rstd = rsqrtf(var + 1e-5f);
        float4 o0, o1;
        o0.x = (v0.x - mu) * rstd * ga0.x + bt0.x;
        o0.y = (v0.y - mu) * rstd * ga0.y + bt0.y;
        o0.z = (v0.z - mu) * rstd * ga0.z + bt0.z;
        o0.w = (v0.w - mu) * rstd * ga0.w + bt0.w;
        o1.x = (v1.x - mu) * rstd * ga1.x + bt1.x;
        o1.y = (v1.y - mu) * rstd * ga1.y + bt1.y;
        o1.z = (v1.z - mu) * rstd * ga1.z + bt1.z;
        o1.w = (v1.w - mu) * rstd * ga1.w + bt1.w;
        *(float4*)(sX + l * ED + lane * 4)       = o0;
        *(float4*)(sX + l * ED + 128 + lane * 4) = o1;
    }
    __syncthreads();

    // ---- GEMM1: y[l][j] = sum_k xn[l][k] * Wp[j][k] + bp[j] ----
    const int tl = warp;
    const int tj = lane;
    // c[il][0..1] -> cols 4tj..4tj+3 ; c[il][2..3] -> cols 128+4tj..+3
    unsigned long long c[8][4];
    {
        float4 bb0 = *(const float4*)(bp + tj * 4);
        float4 bb1 = *(const float4*)(bp + 128 + tj * 4);
        unsigned long long q0 = pack2(bb0.x, bb0.y);
        unsigned long long q1 = pack2(bb0.z, bb0.w);
        unsigned long long q2 = pack2(bb1.x, bb1.y);
        unsigned long long q3 = pack2(bb1.z, bb1.w);
        #pragma unroll
        for (int il = 0; il < 8; ++il) {
            c[il][0] = q0; c[il][1] = q1; c[il][2] = q2; c[il][3] = q3;
        }
    }

    const float* sXrow = sX + tl * 8 * ED;   // this thread's 8 rows

    for (int k0 = 0; k0 < ED; k0 += KC) {
        // stage Wp chunk transposed: sW[kk][j] = Wp[j][k0+kk]
        // stores: column index = threadIdx.x -> lanes hit distinct banks
        #pragma unroll
        for (int it = 0; it < 8; ++it) {
            float4 v = *(const float4*)(Wp + (size_t)threadIdx.x * ED + k0 + it * 4);
            sW[(it * 4 + 0) * WPAD + threadIdx.x] = v.x;
            sW[(it * 4 + 1) * WPAD + threadIdx.x] = v.y;
            sW[(it * 4 + 2) * WPAD + threadIdx.x] = v.z;
            sW[(it * 4 + 3) * WPAD + threadIdx.x] = v.w;
        }
        __syncthreads();
        #pragma unroll 2
        for (int kk = 0; kk < KC; kk += 4) {
            // A: one broadcast LDS.128 per row covers 4 k-steps (1 wf each)
            float4 a4[8];
            #pragma unroll
            for (int il = 0; il < 8; ++il)
                a4[il] = *(const float4*)(sXrow + il * ED + k0 + kk);
            #pragma unroll
            for (int u = 0; u < 4; ++u) {
                const float* wr = sW + (kk + u) * WPAD;
                float4 b0 = *(const float4*)(wr + tj * 4);        // contiguous 512B
                float4 b1 = *(const float4*)(wr + 128 + tj * 4);  // contiguous 512B
                unsigned long long bq0 = pack2(b0.x, b0.y);
                unsigned long long bq1 = pack2(b0.z, b0.w);
                unsigned long long bq2 = pack2(b1.x, b1.y);
                unsigned long long bq3 = pack2(b1.z, b1.w);
                #pragma unroll
                for (int il = 0; il < 8; ++il) {
                    const float a = (u == 0) ? a4[il].x :
                                    (u == 1) ? a4[il].y :
                                    (u == 2) ? a4[il].z : a4[il].w;
                    unsigned long long aq = pack2(a, a);
                    c[il][0] = fma2(aq, bq0, c[il][0]);
                    c[il][1] = fma2(aq, bq1, c[il][1]);
                    c[il][2] = fma2(aq, bq2, c[il][2]);
                    c[il][3] = fma2(aq, bq3, c[il][3]);
                }
            }
        }
        __syncthreads();
    }

    // ---- stage y back into sX (xn dead); contiguous conflict-free stores ----
    #pragma unroll
    for (int il = 0; il < 8; ++il) {
        float* yr = sX + (tl * 8 + il) * ED;
        float4 o0 = make_float4(lo32(c[il][0]), hi32(c[il][0]),
                                lo32(c[il][1]), hi32(c[il][1]));
        float4 o1 = make_float4(lo32(c[il][2]), hi32(c[il][2]),
                                lo32(c[il][3]), hi32(c[il][3]));
        *(float4*)(yr + tj * 4)       = o0;
        *(float4*)(yr + 128 + tj * 4) = o1;
    }
    __syncthreads();

    // ---- GEMM2: z[p][j] = sum_q A[p][q] * y[q][j] ----
    #pragma unroll
    for (int il = 0; il < 8; ++il) {
        c[il][0] = 0ull; c[il][1] = 0ull; c[il][2] = 0ull; c[il][3] = 0ull;
    }
    const float* sArow = sA + tl * 8 * L;
    #pragma unroll 2
    for (int q = 0; q < L; q += 4) {
        float4 a4[8];
        #pragma unroll
        for (int il = 0; il < 8; ++il)
            a4[il] = *(const float4*)(sArow + il * L + q);
        #pragma unroll
        for (int u = 0; u < 4; ++u) {
            const float* yr = sX + (q + u) * ED;
            float4 b0 = *(const float4*)(yr + tj * 4);
            float4 b1 = *(const float4*)(yr + 128 + tj * 4);
            unsigned long long bq0 = pack2(b0.x, b0.y);
            unsigned long long bq1 = pack2(b0.z, b0.w);
            unsigned long long bq2 = pack2(b1.x, b1.y);
            unsigned long long bq3 = pack2(b1.z, b1.w);
            #pragma unroll
            for (int il = 0; il < 8; ++il) {
                const float a = (u == 0) ? a4[il].x :
                                (u == 1) ? a4[il].y :
                                (u == 2) ? a4[il].z : a4[il].w;
                unsigned long long aq = pack2(a, a);
                c[il][0] = fma2(aq, bq0, c[il][0]);
                c[il][1] = fma2(aq, bq1, c[il][1]);
                c[il][2] = fma2(aq, bq2, c[il][2]);
                c[il][3] = fma2(aq, bq3, c[il][3]);
            }
        }
    }

    // ---- windowed write-back (contiguous 512B per warp-row segment) ----
    #pragma unroll
    for (int il = 0; il < 8; ++il) {
        const int p = tl * 8 + il;
        float* orow = obase + (((p >> 4) * 64 + (p & 15)) << 8);
        float4 o0 = make_float4(lo32(c[il][0]), hi32(c[il][0]),
                                lo32(c[il][1]), hi32(c[il][1]));
        float4 o1 = make_float4(lo32(c[il][2]), hi32(c[il][2]),
                                lo32(c[il][3]), hi32(c[il][3]));
        *(float4*)(orow + tj * 4)       = o0;
        *(float4*)(orow + 128 + tj * 4) = o1;
    }
}

// ---------------------------------------------------------------------------
extern "C" void kernel_launch(void* const* d_in, const int* in_sizes, int n_in,
                              void* d_out, int out_size)
{
    (void)in_sizes; (void)n_in; (void)out_size;
    const float* x     = (const float*)d_in[0];
    const float* gamma = (const float*)d_in[1];
    const float* beta  = (const float*)d_in[2];
    const float* Wp    = (const float*)d_in[3];
    const float* bp    = (const float*)d_in[4];
    const float* eb    = (const float*)d_in[5];
    const float* deg   = (const float*)d_in[6];
    float* out = (float*)d_out;

    const size_t smem_bytes = (size_t)(L * ED + KC * WPAD + L * L) * sizeof(float); // 115200
    cudaFuncSetAttribute(window_kernel,
                         cudaFuncAttributeMaxDynamicSharedMemorySize,
                         (int)smem_bytes);

    precompute_A_kernel<<<NWIN, TPB>>>(deg, eb);
    window_kernel<<<2048, TPB, smem_bytes>>>(x, gamma, beta, Wp, bp, out);
}